// round 16
// baseline (speedup 1.0000x reference)
#include <cuda_runtime.h>
#include <cuda_fp16.h>
#include <cstdint>

// ---------------- problem constants ----------------
#define NBATCH 1024
#define NT     65
#define CH     768
#define NH     12
#define DH     64
#define BLDC   4232   // padded bias row stride

// ---------------- fp32 scratch ----------------
__device__ __align__(16) float g_lat1[524288];    // [1024,512]
__device__ __align__(16) float g_lat2[3145728];   // [1024,3072]

// ---------------- fp16 scratch ----------------
__device__ __align__(16) __half g_biash[52002816]; // [B*H][4232]
__device__ __align__(16) __half g_qkvh[153354240]; // [66560][2304] packed q|k|v
__device__ __align__(16) __half g_xbf[51118080];   // 66560 x 768
__device__ __align__(16) __half g_attbf[51118080]; // 66560 x 768
__device__ __align__(16) __half g_clsbf[786432];
__device__ __align__(16) __half g_l1bf[524288];
__device__ __align__(16) __half g_l2bf[3145728];
__device__ __align__(16) __half g_wqkv[1769472];
__device__ __align__(16) __half g_wproj[589824];
__device__ __align__(16) __half g_w1bf[393216];
__device__ __align__(16) __half g_w2bf[1572864];
__device__ __align__(16) __half g_wbbf[1114112];

// ---------------- helpers ----------------
__device__ __forceinline__ uint32_t s2u(const void* p) {
    uint32_t a;
    asm("{ .reg .u64 t; cvta.to.shared.u64 t, %1; cvt.u32.u64 %0, t; }" : "=r"(a) : "l"(p));
    return a;
}
__device__ __forceinline__ void ldsm4(uint32_t* r, uint32_t addr) {
    asm volatile("ldmatrix.sync.aligned.m8n8.x4.shared.b16 {%0,%1,%2,%3}, [%4];"
        : "=r"(r[0]), "=r"(r[1]), "=r"(r[2]), "=r"(r[3]) : "r"(addr));
}
__device__ __forceinline__ void mma16816(float* d, const uint32_t* a, uint32_t b0, uint32_t b1) {
    asm volatile(
        "mma.sync.aligned.m16n8k16.row.col.f32.f16.f16.f32 "
        "{%0,%1,%2,%3}, {%4,%5,%6,%7}, {%8,%9}, {%0,%1,%2,%3};"
        : "+f"(d[0]), "+f"(d[1]), "+f"(d[2]), "+f"(d[3])
        : "r"(a[0]), "r"(a[1]), "r"(a[2]), "r"(a[3]), "r"(b0), "r"(b1));
}

// ---------------- fp32 -> fp16 plain ----------------
__global__ void conv16(const float* __restrict__ src, int lds,
                       __half* __restrict__ dst, int K, int rowsValid)
{
    const int r = blockIdx.x;
    const float4* s = (const float4*)(src + (size_t)r * lds);
    __half2* d = (__half2*)(dst + (size_t)r * K);
    const bool valid = r < rowsValid;
    for (int c = threadIdx.x; c < K / 4; c += blockDim.x) {
        float4 v = valid ? s[c] : make_float4(0.f, 0.f, 0.f, 0.f);
        d[c * 2]     = __half2(__float2half(v.x), __float2half(v.y));
        d[c * 2 + 1] = __half2(__float2half(v.z), __float2half(v.w));
    }
}

// ---------------- 128-thread fp16 GEMM (side path): C = A @ B^T ----------------
#define KC    32
#define LDS_  40
#define APART 10240u
#define NSTG  3
#define TS_   136

template<int MODE, int PASSES>
__global__ __launch_bounds__(128, 2)
void gemm_mma(const __half* __restrict__ A, int lda,
              const __half* __restrict__ B, int ldb,
              void* __restrict__ Cv, int ldc, int M, int N, int K)
{
    constexpr int NPARTS = PASSES + 1;
    constexpr uint32_t STGB = NPARTS * APART;

    extern __shared__ char dynsm[];
    const uint32_t sbase = s2u(dynsm);

    const int tid = threadIdx.x, wid = tid >> 5, lane = tid & 31;
    const int wm = wid & 1, wn = wid >> 1;
    const int bm = blockIdx.y * 128, bn = blockIdx.x * 128;
    const int nk = K / KC;

    float acc[4][8][4];
#pragma unroll
    for (int i = 0; i < 4; i++)
#pragma unroll
        for (int j = 0; j < 8; j++)
#pragma unroll
            for (int e = 0; e < 4; e++) acc[i][j][e] = 0.f;

    auto loads = [&](int t) {
        const uint32_t ub = sbase + (uint32_t)(t % NSTG) * STGB;
        const int kOff = t * KC;
#pragma unroll
        for (int i = 0; i < 4 * NPARTS; i++) {
            const int idx = tid + i * 128;
            const int part = idx >> 9;
            const int id2 = idx & 511;
            const int r = id2 >> 2, cc = id2 & 3;
            const uint32_t dst = ub + (uint32_t)part * APART +
                                 (uint32_t)(r * LDS_ + cc * 8) * 2;
            const void* g = (part == NPARTS - 1)
                ? (const void*)(B + (size_t)(bn + r) * ldb + kOff + cc * 8)
                : (const void*)(A + (size_t)(bm + r) * lda + part * K + kOff + cc * 8);
            asm volatile("cp.async.cg.shared.global [%0], [%1], 16;" :: "r"(dst), "l"(g));
        }
        asm volatile("cp.async.commit_group;");
    };

    loads(0);
    if (nk > 1) loads(1);

    for (int t = 0; t < nk; ++t) {
        if (t + 1 < nk) asm volatile("cp.async.wait_group 1;");
        else            asm volatile("cp.async.wait_group 0;");
        __syncthreads();
        if (t + 2 < nk) loads(t + 2);

        const uint32_t ub  = sbase + (uint32_t)(t % NSTG) * STGB;
        const uint32_t uAh = ub + (uint32_t)(wm * 64 * LDS_) * 2;
        const uint32_t uAl = uAh + APART;
        const uint32_t uB  = ub + (NPARTS - 1) * APART + (uint32_t)(wn * 64 * LDS_) * 2;
#pragma unroll
        for (int ks = 0; ks < 2; ++ks) {
            uint32_t ah[4][4], al[4][4], b[4][4];
#pragma unroll
            for (int mt = 0; mt < 4; ++mt) {
                const uint32_t ro = (uint32_t)((mt * 16 + (lane & 15)) * LDS_ +
                                               ks * 16 + (lane >> 4) * 8) * 2;
                ldsm4(ah[mt], uAh + ro);
                if (PASSES == 2) ldsm4(al[mt], uAl + ro);
            }
#pragma unroll
            for (int ng = 0; ng < 4; ++ng) {
                const uint32_t addr = uB +
                    (uint32_t)((ng * 16 + ((lane >> 4) & 1) * 8 + (lane & 7)) * LDS_ +
                               ks * 16 + ((lane >> 3) & 1) * 8) * 2;
                ldsm4(b[ng], addr);
            }
#pragma unroll
            for (int mt = 0; mt < 4; ++mt)
#pragma unroll
                for (int nt = 0; nt < 8; ++nt) {
                    const uint32_t b0 = b[nt >> 1][(nt & 1) * 2];
                    const uint32_t b1 = b[nt >> 1][(nt & 1) * 2 + 1];
                    mma16816(acc[mt][nt], ah[mt], b0, b1);
                    if (PASSES == 2) mma16816(acc[mt][nt], al[mt], b0, b1);
                }
        }
    }

    const int gr = lane >> 2, gc = (lane & 3) * 2;
    if (MODE == 1) {
        float* C = (float*)Cv;
#pragma unroll
        for (int mt = 0; mt < 4; ++mt)
#pragma unroll
            for (int nt = 0; nt < 8; ++nt)
#pragma unroll
                for (int hp = 0; hp < 2; ++hp) {
                    const int m = bm + wm * 64 + mt * 16 + gr + hp * 8;
                    const int n = bn + wn * 64 + nt * 8 + gc;
                    if (n + 1 < N) {
                        float2 v2 = make_float2(acc[mt][nt][hp * 2], acc[mt][nt][hp * 2 + 1]);
                        *(float2*)&C[(size_t)m * ldc + n] = v2;
                    } else if (n < N) {
                        C[(size_t)m * ldc + n] = acc[mt][nt][hp * 2];
                    }
                }
    } else {
        __syncthreads();
        __half* tile = (__half*)dynsm;
#pragma unroll
        for (int mt = 0; mt < 4; ++mt)
#pragma unroll
            for (int nt = 0; nt < 8; ++nt)
#pragma unroll
                for (int hp = 0; hp < 2; ++hp) {
                    const int ml = wm * 64 + mt * 16 + gr + hp * 8;
                    const int nl = wn * 64 + nt * 8 + gc;
                    *(__half2*)&tile[ml * TS_ + nl] =
                        __floats2half2_rn(acc[mt][nt][hp * 2], acc[mt][nt][hp * 2 + 1]);
                }
        __syncthreads();
        __half* C = (__half*)Cv;
        for (int i = tid; i < 2048; i += 128) {
            const int r = i >> 4;
            const int c = (i & 15) << 3;
            const int n = bn + c;
            const size_t off = (size_t)(bm + r) * ldc + n;
            if (n + 7 < N) {
                *(uint4*)&C[off] = *(const uint4*)&tile[r * TS_ + c];
            } else if (n < N) {
#pragma unroll
                for (int e = 0; e < 8; ++e)
                    if (n + e < N) C[off + e] = tile[r * TS_ + c + e];
            }
        }
    }
}

// ---------------- 256-thread fp16 GEMM, 128x256 CTA tile ----------------
// MODE 1: fp32 float2 store. MODE 2: staged fp16 coalesced store.
#define A2PART 10240u
#define B2PART 20480u
#define STGB2  30720u
#define GEMM2_SMEM (3 * 30720)   // 92160
#define TS2    264               // staging stride (halves)

template<int MODE>
__global__ __launch_bounds__(256, 2)
void gemm_mma256(const __half* __restrict__ A, int lda,
                 const __half* __restrict__ B, int ldb,
                 void* __restrict__ Cv, int ldc, int M, int N, int K)
{
    extern __shared__ char dynsm[];
    const uint32_t sbase = s2u(dynsm);

    const int tid = threadIdx.x, wid = tid >> 5, lane = tid & 31;
    const int wm = wid & 1, wn = wid >> 1;           // 2 x 4 warps; tile 128 x 256
    const int bm = blockIdx.y * 128, bn = blockIdx.x * 256;
    const int nk = K / KC;

    float acc[4][8][4];
#pragma unroll
    for (int i = 0; i < 4; i++)
#pragma unroll
        for (int j = 0; j < 8; j++)
#pragma unroll
            for (int e = 0; e < 4; e++) acc[i][j][e] = 0.f;

    // per chunk: A 128x32 (512 x16B) + B 256x32 (1024 x16B) = 1536; 6 per thread
    auto loads = [&](int t) {
        const uint32_t ub = sbase + (uint32_t)(t % NSTG) * STGB2;
        const int kOff = t * KC;
#pragma unroll
        for (int i = 0; i < 6; i++) {
            const int idx = tid + i * 256;
            if (idx < 512) {
                const int r = idx >> 2, cc = idx & 3;
                const uint32_t dst = ub + (uint32_t)(r * LDS_ + cc * 8) * 2;
                const void* g = (const void*)(A + (size_t)(bm + r) * lda + kOff + cc * 8);
                asm volatile("cp.async.cg.shared.global [%0], [%1], 16;" :: "r"(dst), "l"(g));
            } else {
                const int id2 = idx - 512;
                const int r = id2 >> 2, cc = id2 & 3;
                const uint32_t dst = ub + A2PART + (uint32_t)(r * LDS_ + cc * 8) * 2;
                const void* g = (const void*)(B + (size_t)(bn + r) * ldb + kOff + cc * 8);
                asm volatile("cp.async.cg.shared.global [%0], [%1], 16;" :: "r"(dst), "l"(g));
            }
        }
        asm volatile("cp.async.commit_group;");
    };

    loads(0);
    if (nk > 1) loads(1);

    for (int t = 0; t < nk; ++t) {
        if (t + 1 < nk) asm volatile("cp.async.wait_group 1;");
        else            asm volatile("cp.async.wait_group 0;");
        __syncthreads();
        if (t + 2 < nk) loads(t + 2);

        const uint32_t ub = sbase + (uint32_t)(t % NSTG) * STGB2;
        const uint32_t uA = ub + (uint32_t)(wm * 64 * LDS_) * 2;
        const uint32_t uB = ub + A2PART + (uint32_t)(wn * 64 * LDS_) * 2;
#pragma unroll
        for (int ks = 0; ks < 2; ++ks) {
            uint32_t a[4][4], b[4][4];
#pragma unroll
            for (int mt = 0; mt < 4; ++mt) {
                const uint32_t ro = (uint32_t)((mt * 16 + (lane & 15)) * LDS_ +
                                               ks * 16 + (lane >> 4) * 8) * 2;
                ldsm4(a[mt], uA + ro);
            }
#pragma unroll
            for (int ng = 0; ng < 4; ++ng) {
                const uint32_t addr = uB +
                    (uint32_t)((ng * 16 + ((lane >> 4) & 1) * 8 + (lane & 7)) * LDS_ +
                               ks * 16 + ((lane >> 3) & 1) * 8) * 2;
                ldsm4(b[ng], addr);
            }
#pragma unroll
            for (int mt = 0; mt < 4; ++mt)
#pragma unroll
                for (int nt = 0; nt < 8; ++nt)
                    mma16816(acc[mt][nt], a[mt],
                             b[nt >> 1][(nt & 1) * 2], b[nt >> 1][(nt & 1) * 2 + 1]);
        }
    }

    const int gr = lane >> 2, gc = (lane & 3) * 2;
    if (MODE == 1) {
        float* C = (float*)Cv;
#pragma unroll
        for (int mt = 0; mt < 4; ++mt)
#pragma unroll
            for (int nt = 0; nt < 8; ++nt)
#pragma unroll
                for (int hp = 0; hp < 2; ++hp) {
                    const int m = bm + wm * 64 + mt * 16 + gr + hp * 8;
                    const int n = bn + wn * 64 + nt * 8 + gc;
                    if (n + 1 < N) {
                        float2 v2 = make_float2(acc[mt][nt][hp * 2], acc[mt][nt][hp * 2 + 1]);
                        *(float2*)&C[(size_t)m * ldc + n] = v2;
                    } else if (n < N) {
                        C[(size_t)m * ldc + n] = acc[mt][nt][hp * 2];
                    }
                }
    } else {
        __syncthreads();
        __half* tile = (__half*)dynsm;   // 128 x TS2
#pragma unroll
        for (int mt = 0; mt < 4; ++mt)
#pragma unroll
            for (int nt = 0; nt < 8; ++nt)
#pragma unroll
                for (int hp = 0; hp < 2; ++hp) {
                    const int ml = wm * 64 + mt * 16 + gr + hp * 8;
                    const int nl = wn * 64 + nt * 8 + gc;
                    *(__half2*)&tile[ml * TS2 + nl] =
                        __floats2half2_rn(acc[mt][nt][hp * 2], acc[mt][nt][hp * 2 + 1]);
                }
        __syncthreads();
        __half* C = (__half*)Cv;
        for (int i = tid; i < 4096; i += 256) {
            const int r = i >> 5;
            const int c = (i & 31) << 3;
            const int n = bn + c;
            const size_t off = (size_t)(bm + r) * ldc + n;
            if (n + 7 < N) {
                *(uint4*)&C[off] = *(const uint4*)&tile[r * TS2 + c];
            } else if (n < N) {
#pragma unroll
                for (int e = 0; e < 8; ++e)
                    if (n + e < N) C[off + e] = tile[r * TS2 + c + e];
            }
        }
    }
}

// ---------------- block reduce helper ----------------
__device__ __forceinline__ float2 block_reduce2(float s, float ss, float* shm)
{
#pragma unroll
    for (int o = 16; o; o >>= 1) {
        s  += __shfl_xor_sync(0xffffffffu, s,  o);
        ss += __shfl_xor_sync(0xffffffffu, ss, o);
    }
    const int w = threadIdx.x >> 5, lane = threadIdx.x & 31;
    if (lane == 0) { shm[w] = s; shm[8 + w] = ss; }
    __syncthreads();
    if (threadIdx.x < 32) {
        s  = (lane < 8) ? shm[lane]     : 0.f;
        ss = (lane < 8) ? shm[8 + lane] : 0.f;
#pragma unroll
        for (int o = 4; o; o >>= 1) {
            s  += __shfl_xor_sync(0xffffffffu, s,  o);
            ss += __shfl_xor_sync(0xffffffffu, ss, o);
        }
        if (lane == 0) { shm[0] = s; shm[1] = ss; }
    }
    __syncthreads();
    return make_float2(shm[0], shm[1]);
}

__global__ __launch_bounds__(256)
void ln_silu512(float* __restrict__ data, const float* __restrict__ g, const float* __restrict__ b)
{
    __shared__ float shm[16];
    const int row = blockIdx.x, tid = threadIdx.x;
    float* p = data + (size_t)row * 512;
    float x0 = p[tid], x1 = p[tid + 256];
    float2 r = block_reduce2(x0 + x1, x0 * x0 + x1 * x1, shm);
    const float mean = r.x * (1.f / 512.f);
    const float var  = r.y * (1.f / 512.f) - mean * mean;
    const float inv  = rsqrtf(var + 1e-5f);
    float y0 = (x0 - mean) * inv * g[tid]       + b[tid];
    float y1 = (x1 - mean) * inv * g[tid + 256] + b[tid + 256];
    p[tid]       = y0 / (1.f + __expf(-y0));
    p[tid + 256] = y1 / (1.f + __expf(-y1));
}

__global__ __launch_bounds__(256)
void ln3072(float* __restrict__ data, const float* __restrict__ g, const float* __restrict__ b)
{
    __shared__ float shm[16];
    const int row = blockIdx.x, tid = threadIdx.x;
    float* p = data + (size_t)row * 3072;
    float x[12];
    float s = 0.f, ss = 0.f;
#pragma unroll
    for (int i = 0; i < 12; i++) {
        x[i] = p[tid + i * 256];
        s += x[i]; ss += x[i] * x[i];
    }
    float2 r = block_reduce2(s, ss, shm);
    const float mean = r.x * (1.f / 3072.f);
    const float var  = r.y * (1.f / 3072.f) - mean * mean;
    const float inv  = rsqrtf(var + 1e-5f);
#pragma unroll
    for (int i = 0; i < 12; i++) {
        const int c = tid + i * 256;
        p[c] = (x[i] - mean) * inv * g[c] + b[c];
    }
}

// ---------------- tensor-core fused attention ----------------
#define ATT_SQ 72
#define ATT_SP 88
#define ATT_OQ 0
#define ATT_OK 11520
#define ATT_OV 23040
#define ATT_OP 34304
#define ATT_SMEM 48384

__global__ __launch_bounds__(160)
void attn_kernel(const float* __restrict__ qn_g, const float* __restrict__ qn_b,
                 const float* __restrict__ kn_g, const float* __restrict__ kn_b)
{
    extern __shared__ __align__(16) char asm_[];
    __half* hQ = (__half*)(asm_ + ATT_OQ);
    __half* hK = (__half*)(asm_ + ATT_OK);
    __half* hV = (__half*)(asm_ + ATT_OV);
    __half* hP = (__half*)(asm_ + ATT_OP);
    const uint32_t uQ = s2u(hQ), uK = s2u(hK), uV = s2u(hV), uP = s2u(hP);

    const int bh  = blockIdx.x;
    const int tid = threadIdx.x;
    const int w = tid >> 5, lane = tid & 31;
    const int b = bh / NH, h = bh - b * NH;

    const __half* gq = g_qkvh + (size_t)(b * NT) * 2304 + h * DH;
    const __half* gk = gq + CH;
    const __half* gv = gk + CH;

    {
        const uint4 z = make_uint4(0, 0, 0, 0);
        uint4* pV = (uint4*)(asm_ + ATT_OV);
        for (int i = tid; i < 704; i += 160) pV[i] = z;
        uint4* pQ = (uint4*)(asm_ + ATT_OQ + 65 * ATT_SQ * 2);
        uint4* pK = (uint4*)(asm_ + ATT_OK + 65 * ATT_SQ * 2);
        for (int i = tid; i < 135; i += 160) { pQ[i] = z; pK[i] = z; }
    }
    __syncthreads();

    {
        const float qg0 = qn_g[lane], qg1 = qn_g[lane + 32];
        const float qb0 = qn_b[lane], qb1 = qn_b[lane + 32];
        const float kg0 = kn_g[lane], kg1 = kn_g[lane + 32];
        const float kb0 = kn_b[lane], kb1 = kn_b[lane + 32];
        for (int r = w; r < NT; r += 5) {
            float x0 = __half2float(gq[r * 2304 + lane]);
            float x1 = __half2float(gq[r * 2304 + lane + 32]);
            float s = x0 + x1, ss = x0 * x0 + x1 * x1;
#pragma unroll
            for (int o = 16; o; o >>= 1) {
                s  += __shfl_xor_sync(0xffffffffu, s,  o);
                ss += __shfl_xor_sync(0xffffffffu, ss, o);
            }
            float mean = s * (1.f / 64.f);
            float inv  = rsqrtf(ss * (1.f / 64.f) - mean * mean + 1e-5f);
            hQ[r * ATT_SQ + lane]      = __float2half(((x0 - mean) * inv * qg0 + qb0) * 0.125f);
            hQ[r * ATT_SQ + lane + 32] = __float2half(((x1 - mean) * inv * qg1 + qb1) * 0.125f);

            x0 = __half2float(gk[r * 2304 + lane]);
            x1 = __half2float(gk[r * 2304 + lane + 32]);
            s = x0 + x1; ss = x0 * x0 + x1 * x1;
#pragma unroll
            for (int o = 16; o; o >>= 1) {
                s  += __shfl_xor_sync(0xffffffffu, s,  o);
                ss += __shfl_xor_sync(0xffffffffu, ss, o);
            }
            mean = s * (1.f / 64.f);
            inv  = rsqrtf(ss * (1.f / 64.f) - mean * mean + 1e-5f);
            hK[r * ATT_SQ + lane]      = __float2half((x0 - mean) * inv * kg0 + kb0);
            hK[r * ATT_SQ + lane + 32] = __float2half((x1 - mean) * inv * kg1 + kb1);

            hV[lane * ATT_SP + r]        = gv[r * 2304 + lane];
            hV[(lane + 32) * ATT_SP + r] = gv[r * 2304 + lane + 32];
        }
    }
    __syncthreads();

    const __half* bp = g_biash + (size_t)bh * BLDC;
    const int gr = lane >> 2, gc = (lane & 3) * 2;
    const int mt = w;

    float acc[9][4];
#pragma unroll
    for (int nt = 0; nt < 9; ++nt)
#pragma unroll
        for (int e = 0; e < 4; ++e) acc[nt][e] = 0.f;
#pragma unroll
    for (int kt = 0; kt < 4; ++kt) {
        uint32_t a[4];
        ldsm4(a, uQ + (uint32_t)((mt * 16 + (lane & 15)) * ATT_SQ + kt * 16 + (lane >> 4) * 8) * 2);
        uint32_t bf[5][4];
#pragma unroll
        for (int ng = 0; ng < 5; ++ng)
            ldsm4(bf[ng], uK + (uint32_t)((ng * 16 + ((lane >> 4) & 1) * 8 + (lane & 7)) * ATT_SQ +
                                          kt * 16 + ((lane >> 3) & 1) * 8) * 2);
#pragma unroll
        for (int nt = 0; nt < 9; ++nt)
            mma16816(acc[nt], a, bf[nt >> 1][(nt & 1) * 2], bf[nt >> 1][(nt & 1) * 2 + 1]);
    }
#pragma unroll
    for (int nt = 0; nt < 9; ++nt)
#pragma unroll
        for (int e = 0; e < 4; ++e) {
            const int i = mt * 16 + gr + (e >> 1) * 8;
            const int j = nt * 8 + gc + (e & 1);
            if (j >= NT)      acc[nt][e] = -1e30f;
            else if (i < NT)  acc[nt][e] += __half2float(bp[i * NT + j]);
        }
#pragma unroll
    for (int hp = 0; hp < 2; ++hp) {
        const int e0 = hp * 2;
        float mx = -1e30f;
#pragma unroll
        for (int nt = 0; nt < 9; ++nt)
            mx = fmaxf(mx, fmaxf(acc[nt][e0], acc[nt][e0 + 1]));
        mx = fmaxf(mx, __shfl_xor_sync(0xffffffffu, mx, 1));
        mx = fmaxf(mx, __shfl_xor_sync(0xffffffffu, mx, 2));
        float sum = 0.f;
#pragma unroll
        for (int nt = 0; nt < 9; ++nt) {
            acc[nt][e0]     = __expf(acc[nt][e0]     - mx);
            acc[nt][e0 + 1] = __expf(acc[nt][e0 + 1] - mx);
            sum += acc[nt][e0] + acc[nt][e0 + 1];
        }
        sum += __shfl_xor_sync(0xffffffffu, sum, 1);
        sum += __shfl_xor_sync(0xffffffffu, sum, 2);
        const float inv = 1.f / sum;
        const int row = mt * 16 + gr + hp * 8;
#pragma unroll
        for (int nt = 0; nt < 9; ++nt)
            *(__half2*)&hP[row * ATT_SP + nt * 8 + gc] =
                __floats2half2_rn(acc[nt][e0] * inv, acc[nt][e0 + 1] * inv);
        *(__half2*)&hP[row * ATT_SP + 72 + gc] = __floats2half2_rn(0.f, 0.f);
    }
    __syncwarp();

    float oc[8][4];
#pragma unroll
    for (int nt = 0; nt < 8; ++nt)
#pragma unroll
        for (int e = 0; e < 4; ++e) oc[nt][e] = 0.f;
#pragma unroll
    for (int kt = 0; kt < 5; ++kt) {
        uint32_t a[4];
        ldsm4(a, uP + (uint32_t)((mt * 16 + (lane & 15)) * ATT_SP + kt * 16 + (lane >> 4) * 8) * 2);
        uint32_t bf[4][4];
#pragma unroll
        for (int ng = 0; ng < 4; ++ng)
            ldsm4(bf[ng], uV + (uint32_t)((ng * 16 + ((lane >> 4) & 1) * 8 + (lane & 7)) * ATT_SP +
                                          kt * 16 + ((lane >> 3) & 1) * 8) * 2);
#pragma unroll
        for (int nt = 0; nt < 8; ++nt)
            mma16816(oc[nt], a, bf[nt >> 1][(nt & 1) * 2], bf[nt >> 1][(nt & 1) * 2 + 1]);
    }
#pragma unroll
    for (int hp = 0; hp < 2; ++hp) {
        const int i = mt * 16 + gr + hp * 8;
        if (i < NT) {
            __half* oh = g_attbf + ((size_t)(b * NT + i)) * CH + h * DH;
#pragma unroll
            for (int nt = 0; nt < 8; ++nt)
                *(__half2*)&oh[nt * 8 + gc] =
                    __floats2half2_rn(oc[nt][hp * 2], oc[nt][hp * 2 + 1]);
        }
    }
}

// ---------------- host launcher ----------------
extern "C" void kernel_launch(void* const* d_in, const int* in_sizes, int n_in,
                              void* d_out, int out_size)
{
    const float* x       = (const float*)d_in[0];
    const float* qkv_w   = (const float*)d_in[1];
    const float* proj_w  = (const float*)d_in[2];
    const float* qn_g    = (const float*)d_in[3];
    const float* qn_b    = (const float*)d_in[4];
    const float* kn_g    = (const float*)d_in[5];
    const float* kn_b    = (const float*)d_in[6];
    const float* sg_w1   = (const float*)d_in[7];
    const float* sg_ln1g = (const float*)d_in[8];
    const float* sg_ln1b = (const float*)d_in[9];
    const float* sg_w2   = (const float*)d_in[10];
    const float* sg_ln2g = (const float*)d_in[11];
    const float* sg_ln2b = (const float*)d_in[12];
    const float* sg_bw   = (const float*)d_in[13];
    float* out = (float*)d_out;

    float *p_lat1, *p_lat2;
    cudaGetSymbolAddress((void**)&p_lat1, g_lat1);
    cudaGetSymbolAddress((void**)&p_lat2, g_lat2);
    __half *pbiash, *pqkvh, *pxbf, *pattbf, *pwqkv, *pwproj, *pcls, *pw1, *pl1, *pw2, *pl2, *pwb;
    cudaGetSymbolAddress((void**)&pbiash,g_biash);
    cudaGetSymbolAddress((void**)&pqkvh, g_qkvh);
    cudaGetSymbolAddress((void**)&pxbf,  g_xbf);
    cudaGetSymbolAddress((void**)&pattbf,g_attbf);
    cudaGetSymbolAddress((void**)&pwqkv, g_wqkv);
    cudaGetSymbolAddress((void**)&pwproj,g_wproj);
    cudaGetSymbolAddress((void**)&pcls,  g_clsbf);
    cudaGetSymbolAddress((void**)&pw1,   g_w1bf);
    cudaGetSymbolAddress((void**)&pl1,   g_l1bf);
    cudaGetSymbolAddress((void**)&pw2,   g_w2bf);
    cudaGetSymbolAddress((void**)&pl2,   g_l2bf);
    cudaGetSymbolAddress((void**)&pwb,   g_wbbf);

    const int SM1 = NSTG * 2 * (int)APART;   // 61440
    cudaFuncSetAttribute(gemm_mma<1,1>, cudaFuncAttributeMaxDynamicSharedMemorySize, SM1);
    cudaFuncSetAttribute(gemm_mma<2,1>, cudaFuncAttributeMaxDynamicSharedMemorySize, SM1);
    cudaFuncSetAttribute(gemm_mma256<1>, cudaFuncAttributeMaxDynamicSharedMemorySize, GEMM2_SMEM);
    cudaFuncSetAttribute(gemm_mma256<2>, cudaFuncAttributeMaxDynamicSharedMemorySize, GEMM2_SMEM);
    cudaFuncSetAttribute(attn_kernel, cudaFuncAttributeMaxDynamicSharedMemorySize, ATT_SMEM);

    static cudaStream_t sB = nullptr;
    static cudaEvent_t evFork = nullptr, evJoin = nullptr;
    if (sB == nullptr) {
        cudaStreamCreateWithFlags(&sB, cudaStreamNonBlocking);
        cudaEventCreateWithFlags(&evFork, cudaEventDisableTiming);
        cudaEventCreateWithFlags(&evJoin, cudaEventDisableTiming);
    }

    cudaEventRecord(evFork, 0);
    cudaStreamWaitEvent(sB, evFork, 0);

    // --- side stream: bias path + proj weight conversion ---
    conv16<<<1024, 192, 0, sB>>>(x, NT * CH, pcls, CH, 1024);
    conv16<<<512, 192, 0, sB>>>(sg_w1, CH, pw1, CH, 512);
    conv16<<<768, 192, 0, sB>>>(proj_w, CH, pwproj, CH, 768);
    gemm_mma<1,1><<<dim3(4, 8), 128, SM1, sB>>>(pcls, 768, pw1, 768, p_lat1, 512, 1024, 512, 768);
    ln_silu512<<<1024, 256, 0, sB>>>(p_lat1, sg_ln1g, sg_ln1b);
    conv16<<<1024, 128, 0, sB>>>(p_lat1, 512, pl1, 512, 1024);
    conv16<<<3072, 128, 0, sB>>>(sg_w2, 512, pw2, 512, 3072);
    gemm_mma<1,1><<<dim3(24, 8), 128, SM1, sB>>>(pl1, 512, pw2, 512, p_lat2, 3072, 1024, 3072, 512);
    ln3072<<<1024, 256, 0, sB>>>(p_lat2, sg_ln2g, sg_ln2b);
    conv16<<<12288, 64, 0, sB>>>(p_lat2, 256, pl2, 256, 12288);
    conv16<<<4352, 64, 0, sB>>>(sg_bw, 256, pwb, 256, 4225);
    gemm_mma<2,1><<<dim3(34, 96), 128, SM1, sB>>>(pl2, 256, pwb, 256, pbiash, BLDC, 12288, 4225, 256);
    cudaEventRecord(evJoin, sB);

    // --- main stream: qkv path (wide-tile GEMM, packed fp16 output) ---
    conv16<<<66560, 192>>>(x, CH, pxbf, CH, 66560);
    conv16<<<2304, 192>>>(qkv_w, CH, pwqkv, CH, 2304);
    gemm_mma256<2><<<dim3(9, 520), 256, GEMM2_SMEM>>>(pxbf, 768, pwqkv, 768, pqkvh, 2304, 66560, 2304, 768);

    cudaStreamWaitEvent(0, evJoin, 0);
    attn_kernel<<<NBATCH * NH, 160, ATT_SMEM>>>(qn_g, qn_b, kn_g, kn_b);

    // --- output projection (wide-tile) ---
    gemm_mma256<1><<<dim3(3, 520), 256, GEMM2_SMEM>>>(pattbf, 768, pwproj, 768, out, 768, 66560, 768, 768);
}

// round 17
// speedup vs baseline: 1.7737x; 1.7737x over previous
#include <cuda_runtime.h>
#include <cuda_fp16.h>
#include <cstdint>

// ---------------- problem constants ----------------
#define NBATCH 1024
#define NT     65
#define CH     768
#define NH     12
#define DH     64
#define BLDC   4232   // padded bias row stride (16B-aligned rows)

// ---------------- fp32 scratch ----------------
__device__ __align__(16) float g_lat1[524288];    // [1024,512]
__device__ __align__(16) float g_lat2[3145728];   // [1024,3072]

// ---------------- fp16 scratch ----------------
__device__ __align__(16) __half g_biash[52002816]; // [B*H][4232] fp16 (4225 used)
__device__ __align__(16) __half g_qkvh[153354240]; // [66560][2304] packed q|k|v fp16
__device__ __align__(16) __half g_xbf[51118080];   // 66560 x 768
__device__ __align__(16) __half g_attbf[51118080]; // 66560 x 768 (by attn)
__device__ __align__(16) __half g_clsbf[786432];   // 1024 x 768
__device__ __align__(16) __half g_l1bf[524288];    // 1024 x 512
__device__ __align__(16) __half g_l2bf[3145728];   // 12288 x 256
__device__ __align__(16) __half g_wqkv[1769472];   // 2304 x 768
__device__ __align__(16) __half g_wproj[589824];   // 768 x 768
__device__ __align__(16) __half g_w1bf[393216];    // 512 x 768
__device__ __align__(16) __half g_w2bf[1572864];   // 3072 x 512
__device__ __align__(16) __half g_wbbf[1114112];   // 4352 x 256 (rows >= 4225 zero)

// ---------------- helpers ----------------
__device__ __forceinline__ uint32_t s2u(const void* p) {
    uint32_t a;
    asm("{ .reg .u64 t; cvta.to.shared.u64 t, %1; cvt.u32.u64 %0, t; }" : "=r"(a) : "l"(p));
    return a;
}
__device__ __forceinline__ void ldsm4(uint32_t* r, uint32_t addr) {
    asm volatile("ldmatrix.sync.aligned.m8n8.x4.shared.b16 {%0,%1,%2,%3}, [%4];"
        : "=r"(r[0]), "=r"(r[1]), "=r"(r[2]), "=r"(r[3]) : "r"(addr));
}
__device__ __forceinline__ void mma16816(float* d, const uint32_t* a, uint32_t b0, uint32_t b1) {
    asm volatile(
        "mma.sync.aligned.m16n8k16.row.col.f32.f16.f16.f32 "
        "{%0,%1,%2,%3}, {%4,%5,%6,%7}, {%8,%9}, {%0,%1,%2,%3};"
        : "+f"(d[0]), "+f"(d[1]), "+f"(d[2]), "+f"(d[3])
        : "r"(a[0]), "r"(a[1]), "r"(a[2]), "r"(a[3]), "r"(b0), "r"(b1));
}

// ---------------- fp32 -> fp16 plain ----------------
__global__ void conv16(const float* __restrict__ src, int lds,
                       __half* __restrict__ dst, int K, int rowsValid)
{
    const int r = blockIdx.x;
    const float4* s = (const float4*)(src + (size_t)r * lds);
    __half2* d = (__half2*)(dst + (size_t)r * K);
    const bool valid = r < rowsValid;
    for (int c = threadIdx.x; c < K / 4; c += blockDim.x) {
        float4 v = valid ? s[c] : make_float4(0.f, 0.f, 0.f, 0.f);
        d[c * 2]     = __half2(__float2half(v.x), __float2half(v.y));
        d[c * 2 + 1] = __half2(__float2half(v.z), __float2half(v.w));
    }
}

// ---------------- fp16 GEMM: C = A @ B^T ----------------
// MODE 1: fp32 store (float2, guarded). MODE 2: fp16 smem-staged coalesced store.
#define KC    32
#define LDS_  40
#define APART 10240u
#define NSTG  3
#define TS_   136   // staging tile fp16 stride (padded)

template<int MODE, int PASSES>
__global__ __launch_bounds__(128, 2)
void gemm_mma(const __half* __restrict__ A, int lda,
              const __half* __restrict__ B, int ldb,
              void* __restrict__ Cv, int ldc, int M, int N, int K)
{
    constexpr int NPARTS = PASSES + 1;
    constexpr uint32_t STGB = NPARTS * APART;

    extern __shared__ char dynsm[];
    const uint32_t sbase = s2u(dynsm);

    const int tid = threadIdx.x, wid = tid >> 5, lane = tid & 31;
    const int wm = wid & 1, wn = wid >> 1;
    const int bm = blockIdx.y * 128, bn = blockIdx.x * 128;
    const int nk = K / KC;

    float acc[4][8][4];
#pragma unroll
    for (int i = 0; i < 4; i++)
#pragma unroll
        for (int j = 0; j < 8; j++)
#pragma unroll
            for (int e = 0; e < 4; e++) acc[i][j][e] = 0.f;

    auto loads = [&](int t) {
        const uint32_t ub = sbase + (uint32_t)(t % NSTG) * STGB;
        const int kOff = t * KC;
#pragma unroll
        for (int i = 0; i < 4 * NPARTS; i++) {
            const int idx = tid + i * 128;
            const int part = idx >> 9;
            const int id2 = idx & 511;
            const int r = id2 >> 2, cc = id2 & 3;
            const uint32_t dst = ub + (uint32_t)part * APART +
                                 (uint32_t)(r * LDS_ + cc * 8) * 2;
            const void* g = (part == NPARTS - 1)
                ? (const void*)(B + (size_t)(bn + r) * ldb + kOff + cc * 8)
                : (const void*)(A + (size_t)(bm + r) * lda + part * K + kOff + cc * 8);
            asm volatile("cp.async.cg.shared.global [%0], [%1], 16;" :: "r"(dst), "l"(g));
        }
        asm volatile("cp.async.commit_group;");
    };

    loads(0);
    if (nk > 1) loads(1);

    for (int t = 0; t < nk; ++t) {
        if (t + 1 < nk) asm volatile("cp.async.wait_group 1;");
        else            asm volatile("cp.async.wait_group 0;");
        __syncthreads();
        if (t + 2 < nk) loads(t + 2);

        const uint32_t ub  = sbase + (uint32_t)(t % NSTG) * STGB;
        const uint32_t uAh = ub + (uint32_t)(wm * 64 * LDS_) * 2;
        const uint32_t uAl = uAh + APART;
        const uint32_t uB  = ub + (NPARTS - 1) * APART + (uint32_t)(wn * 64 * LDS_) * 2;
#pragma unroll
        for (int ks = 0; ks < 2; ++ks) {
            uint32_t ah[4][4], al[4][4], b[4][4];
#pragma unroll
            for (int mt = 0; mt < 4; ++mt) {
                const uint32_t ro = (uint32_t)((mt * 16 + (lane & 15)) * LDS_ +
                                               ks * 16 + (lane >> 4) * 8) * 2;
                ldsm4(ah[mt], uAh + ro);
                if (PASSES == 2) ldsm4(al[mt], uAl + ro);
            }
#pragma unroll
            for (int ng = 0; ng < 4; ++ng) {
                const uint32_t addr = uB +
                    (uint32_t)((ng * 16 + ((lane >> 4) & 1) * 8 + (lane & 7)) * LDS_ +
                               ks * 16 + ((lane >> 3) & 1) * 8) * 2;
                ldsm4(b[ng], addr);
            }
#pragma unroll
            for (int mt = 0; mt < 4; ++mt)
#pragma unroll
                for (int nt = 0; nt < 8; ++nt) {
                    const uint32_t b0 = b[nt >> 1][(nt & 1) * 2];
                    const uint32_t b1 = b[nt >> 1][(nt & 1) * 2 + 1];
                    mma16816(acc[mt][nt], ah[mt], b0, b1);
                    if (PASSES == 2) mma16816(acc[mt][nt], al[mt], b0, b1);
                }
        }
    }

    const int gr = lane >> 2, gc = (lane & 3) * 2;
    if (MODE == 1) {
        float* C = (float*)Cv;
#pragma unroll
        for (int mt = 0; mt < 4; ++mt)
#pragma unroll
            for (int nt = 0; nt < 8; ++nt)
#pragma unroll
                for (int hp = 0; hp < 2; ++hp) {
                    const int m = bm + wm * 64 + mt * 16 + gr + hp * 8;
                    const int n = bn + wn * 64 + nt * 8 + gc;
                    if (n + 1 < N) {
                        float2 v2 = make_float2(acc[mt][nt][hp * 2], acc[mt][nt][hp * 2 + 1]);
                        *(float2*)&C[(size_t)m * ldc + n] = v2;
                    } else if (n < N) {
                        C[(size_t)m * ldc + n] = acc[mt][nt][hp * 2];
                    }
                }
    } else {
        // staged fp16 epilogue: smem tile -> 16B coalesced writes
        __syncthreads();
        __half* tile = (__half*)dynsm;
#pragma unroll
        for (int mt = 0; mt < 4; ++mt)
#pragma unroll
            for (int nt = 0; nt < 8; ++nt)
#pragma unroll
                for (int hp = 0; hp < 2; ++hp) {
                    const int ml = wm * 64 + mt * 16 + gr + hp * 8;
                    const int nl = wn * 64 + nt * 8 + gc;
                    *(__half2*)&tile[ml * TS_ + nl] =
                        __floats2half2_rn(acc[mt][nt][hp * 2], acc[mt][nt][hp * 2 + 1]);
                }
        __syncthreads();
        __half* C = (__half*)Cv;
        for (int i = tid; i < 2048; i += 128) {
            const int r = i >> 4;
            const int c = (i & 15) << 3;
            const int n = bn + c;
            const size_t off = (size_t)(bm + r) * ldc + n;
            if (n + 7 < N) {
                *(uint4*)&C[off] = *(const uint4*)&tile[r * TS_ + c];
            } else if (n < N) {
#pragma unroll
                for (int e = 0; e < 8; ++e)
                    if (n + e < N) C[off + e] = tile[r * TS_ + c + e];
            }
        }
    }
}

// ---------------- block reduce helper ----------------
__device__ __forceinline__ float2 block_reduce2(float s, float ss, float* shm)
{
#pragma unroll
    for (int o = 16; o; o >>= 1) {
        s  += __shfl_xor_sync(0xffffffffu, s,  o);
        ss += __shfl_xor_sync(0xffffffffu, ss, o);
    }
    const int w = threadIdx.x >> 5, lane = threadIdx.x & 31;
    if (lane == 0) { shm[w] = s; shm[8 + w] = ss; }
    __syncthreads();
    if (threadIdx.x < 32) {
        s  = (lane < 8) ? shm[lane]     : 0.f;
        ss = (lane < 8) ? shm[8 + lane] : 0.f;
#pragma unroll
        for (int o = 4; o; o >>= 1) {
            s  += __shfl_xor_sync(0xffffffffu, s,  o);
            ss += __shfl_xor_sync(0xffffffffu, ss, o);
        }
        if (lane == 0) { shm[0] = s; shm[1] = ss; }
    }
    __syncthreads();
    return make_float2(shm[0], shm[1]);
}

__global__ __launch_bounds__(256)
void ln_silu512(float* __restrict__ data, const float* __restrict__ g, const float* __restrict__ b)
{
    __shared__ float shm[16];
    const int row = blockIdx.x, tid = threadIdx.x;
    float* p = data + (size_t)row * 512;
    float x0 = p[tid], x1 = p[tid + 256];
    float2 r = block_reduce2(x0 + x1, x0 * x0 + x1 * x1, shm);
    const float mean = r.x * (1.f / 512.f);
    const float var  = r.y * (1.f / 512.f) - mean * mean;
    const float inv  = rsqrtf(var + 1e-5f);
    float y0 = (x0 - mean) * inv * g[tid]       + b[tid];
    float y1 = (x1 - mean) * inv * g[tid + 256] + b[tid + 256];
    p[tid]       = y0 / (1.f + __expf(-y0));
    p[tid + 256] = y1 / (1.f + __expf(-y1));
}

__global__ __launch_bounds__(256)
void ln3072(float* __restrict__ data, const float* __restrict__ g, const float* __restrict__ b)
{
    __shared__ float shm[16];
    const int row = blockIdx.x, tid = threadIdx.x;
    float* p = data + (size_t)row * 3072;
    float x[12];
    float s = 0.f, ss = 0.f;
#pragma unroll
    for (int i = 0; i < 12; i++) {
        x[i] = p[tid + i * 256];
        s += x[i]; ss += x[i] * x[i];
    }
    float2 r = block_reduce2(s, ss, shm);
    const float mean = r.x * (1.f / 3072.f);
    const float var  = r.y * (1.f / 3072.f) - mean * mean;
    const float inv  = rsqrtf(var + 1e-5f);
#pragma unroll
    for (int i = 0; i < 12; i++) {
        const int c = tid + i * 256;
        p[c] = (x[i] - mean) * inv * g[c] + b[c];
    }
}

// ---------------- tensor-core fused attention (packed fp16 qkv + fp16 bias) ----------------
// 160 threads = 5 warps, one 16-row m-tile per warp.
// smem (fp16): Q[80][72] | K[80][72] | Vt[64][88] | P[80][88]
#define ATT_SQ 72
#define ATT_SP 88
#define ATT_OQ 0
#define ATT_OK 11520
#define ATT_OV 23040
#define ATT_OP 34304
#define ATT_SMEM 48384

__global__ __launch_bounds__(160)
void attn_kernel(const float* __restrict__ qn_g, const float* __restrict__ qn_b,
                 const float* __restrict__ kn_g, const float* __restrict__ kn_b)
{
    extern __shared__ __align__(16) char asm_[];
    __half* hQ = (__half*)(asm_ + ATT_OQ);
    __half* hK = (__half*)(asm_ + ATT_OK);
    __half* hV = (__half*)(asm_ + ATT_OV);
    __half* hP = (__half*)(asm_ + ATT_OP);
    const uint32_t uQ = s2u(hQ), uK = s2u(hK), uV = s2u(hV), uP = s2u(hP);

    const int bh  = blockIdx.x;
    const int tid = threadIdx.x;
    const int w = tid >> 5, lane = tid & 31;
    const int b = bh / NH, h = bh - b * NH;

    // packed qkv rows: row t of batch b at g_qkvh[(b*NT+t)*2304]; q|k|v at +0,+768,+1536
    const __half* gq = g_qkvh + (size_t)(b * NT) * 2304 + h * DH;
    const __half* gk = gq + CH;
    const __half* gv = gk + CH;

    // zero pads
    {
        const uint4 z = make_uint4(0, 0, 0, 0);
        uint4* pV = (uint4*)(asm_ + ATT_OV);
        for (int i = tid; i < 704; i += 160) pV[i] = z;
        uint4* pQ = (uint4*)(asm_ + ATT_OQ + 65 * ATT_SQ * 2);
        uint4* pK = (uint4*)(asm_ + ATT_OK + 65 * ATT_SQ * 2);
        for (int i = tid; i < 135; i += 160) { pQ[i] = z; pK[i] = z; }
    }
    __syncthreads();

    // LN q (x1/8), k -> fp16 smem; V -> transposed fp16 smem
    {
        const float qg0 = qn_g[lane], qg1 = qn_g[lane + 32];
        const float qb0 = qn_b[lane], qb1 = qn_b[lane + 32];
        const float kg0 = kn_g[lane], kg1 = kn_g[lane + 32];
        const float kb0 = kn_b[lane], kb1 = kn_b[lane + 32];
        for (int r = w; r < NT; r += 5) {
            float x0 = __half2float(gq[r * 2304 + lane]);
            float x1 = __half2float(gq[r * 2304 + lane + 32]);
            float s = x0 + x1, ss = x0 * x0 + x1 * x1;
#pragma unroll
            for (int o = 16; o; o >>= 1) {
                s  += __shfl_xor_sync(0xffffffffu, s,  o);
                ss += __shfl_xor_sync(0xffffffffu, ss, o);
            }
            float mean = s * (1.f / 64.f);
            float inv  = rsqrtf(ss * (1.f / 64.f) - mean * mean + 1e-5f);
            hQ[r * ATT_SQ + lane]      = __float2half(((x0 - mean) * inv * qg0 + qb0) * 0.125f);
            hQ[r * ATT_SQ + lane + 32] = __float2half(((x1 - mean) * inv * qg1 + qb1) * 0.125f);

            x0 = __half2float(gk[r * 2304 + lane]);
            x1 = __half2float(gk[r * 2304 + lane + 32]);
            s = x0 + x1; ss = x0 * x0 + x1 * x1;
#pragma unroll
            for (int o = 16; o; o >>= 1) {
                s  += __shfl_xor_sync(0xffffffffu, s,  o);
                ss += __shfl_xor_sync(0xffffffffu, ss, o);
            }
            mean = s * (1.f / 64.f);
            inv  = rsqrtf(ss * (1.f / 64.f) - mean * mean + 1e-5f);
            hK[r * ATT_SQ + lane]      = __float2half((x0 - mean) * inv * kg0 + kb0);
            hK[r * ATT_SQ + lane + 32] = __float2half((x1 - mean) * inv * kg1 + kb1);

            hV[lane * ATT_SP + r]        = gv[r * 2304 + lane];
            hV[(lane + 32) * ATT_SP + r] = gv[r * 2304 + lane + 32];
        }
    }
    __syncthreads();

    const __half* bp = g_biash + (size_t)bh * BLDC;
    const int gr = lane >> 2, gc = (lane & 3) * 2;
    const int mt = w;

    // ---- S = Q @ K^T ----
    float acc[9][4];
#pragma unroll
    for (int nt = 0; nt < 9; ++nt)
#pragma unroll
        for (int e = 0; e < 4; ++e) acc[nt][e] = 0.f;
#pragma unroll
    for (int kt = 0; kt < 4; ++kt) {
        uint32_t a[4];
        ldsm4(a, uQ + (uint32_t)((mt * 16 + (lane & 15)) * ATT_SQ + kt * 16 + (lane >> 4) * 8) * 2);
        uint32_t bf[5][4];
#pragma unroll
        for (int ng = 0; ng < 5; ++ng)
            ldsm4(bf[ng], uK + (uint32_t)((ng * 16 + ((lane >> 4) & 1) * 8 + (lane & 7)) * ATT_SQ +
                                          kt * 16 + ((lane >> 3) & 1) * 8) * 2);
#pragma unroll
        for (int nt = 0; nt < 9; ++nt)
            mma16816(acc[nt], a, bf[nt >> 1][(nt & 1) * 2], bf[nt >> 1][(nt & 1) * 2 + 1]);
    }
    // ---- bias + column mask ----
#pragma unroll
    for (int nt = 0; nt < 9; ++nt)
#pragma unroll
        for (int e = 0; e < 4; ++e) {
            const int i = mt * 16 + gr + (e >> 1) * 8;
            const int j = nt * 8 + gc + (e & 1);
            if (j >= NT)      acc[nt][e] = -1e30f;
            else if (i < NT)  acc[nt][e] += __half2float(bp[i * NT + j]);
        }
    // ---- softmax ----
#pragma unroll
    for (int hp = 0; hp < 2; ++hp) {
        const int e0 = hp * 2;
        float mx = -1e30f;
#pragma unroll
        for (int nt = 0; nt < 9; ++nt)
            mx = fmaxf(mx, fmaxf(acc[nt][e0], acc[nt][e0 + 1]));
        mx = fmaxf(mx, __shfl_xor_sync(0xffffffffu, mx, 1));
        mx = fmaxf(mx, __shfl_xor_sync(0xffffffffu, mx, 2));
        float sum = 0.f;
#pragma unroll
        for (int nt = 0; nt < 9; ++nt) {
            acc[nt][e0]     = __expf(acc[nt][e0]     - mx);
            acc[nt][e0 + 1] = __expf(acc[nt][e0 + 1] - mx);
            sum += acc[nt][e0] + acc[nt][e0 + 1];
        }
        sum += __shfl_xor_sync(0xffffffffu, sum, 1);
        sum += __shfl_xor_sync(0xffffffffu, sum, 2);
        const float inv = 1.f / sum;
        const int row = mt * 16 + gr + hp * 8;
#pragma unroll
        for (int nt = 0; nt < 9; ++nt)
            *(__half2*)&hP[row * ATT_SP + nt * 8 + gc] =
                __floats2half2_rn(acc[nt][e0] * inv, acc[nt][e0 + 1] * inv);
        *(__half2*)&hP[row * ATT_SP + 72 + gc] = __floats2half2_rn(0.f, 0.f);
    }
    __syncwarp();

    // ---- O = P @ Vt ----
    float oc[8][4];
#pragma unroll
    for (int nt = 0; nt < 8; ++nt)
#pragma unroll
        for (int e = 0; e < 4; ++e) oc[nt][e] = 0.f;
#pragma unroll
    for (int kt = 0; kt < 5; ++kt) {
        uint32_t a[4];
        ldsm4(a, uP + (uint32_t)((mt * 16 + (lane & 15)) * ATT_SP + kt * 16 + (lane >> 4) * 8) * 2);
        uint32_t bf[4][4];
#pragma unroll
        for (int ng = 0; ng < 4; ++ng)
            ldsm4(bf[ng], uV + (uint32_t)((ng * 16 + ((lane >> 4) & 1) * 8 + (lane & 7)) * ATT_SP +
                                          kt * 16 + ((lane >> 3) & 1) * 8) * 2);
#pragma unroll
        for (int nt = 0; nt < 8; ++nt)
            mma16816(oc[nt], a, bf[nt >> 1][(nt & 1) * 2], bf[nt >> 1][(nt & 1) * 2 + 1]);
    }
    // ---- store O fp16 ----
#pragma unroll
    for (int hp = 0; hp < 2; ++hp) {
        const int i = mt * 16 + gr + hp * 8;
        if (i < NT) {
            __half* oh = g_attbf + ((size_t)(b * NT + i)) * CH + h * DH;
#pragma unroll
            for (int nt = 0; nt < 8; ++nt)
                *(__half2*)&oh[nt * 8 + gc] =
                    __floats2half2_rn(oc[nt][hp * 2], oc[nt][hp * 2 + 1]);
        }
    }
}

// ---------------- host launcher ----------------
extern "C" void kernel_launch(void* const* d_in, const int* in_sizes, int n_in,
                              void* d_out, int out_size)
{
    const float* x       = (const float*)d_in[0];
    const float* qkv_w   = (const float*)d_in[1];
    const float* proj_w  = (const float*)d_in[2];
    const float* qn_g    = (const float*)d_in[3];
    const float* qn_b    = (const float*)d_in[4];
    const float* kn_g    = (const float*)d_in[5];
    const float* kn_b    = (const float*)d_in[6];
    const float* sg_w1   = (const float*)d_in[7];
    const float* sg_ln1g = (const float*)d_in[8];
    const float* sg_ln1b = (const float*)d_in[9];
    const float* sg_w2   = (const float*)d_in[10];
    const float* sg_ln2g = (const float*)d_in[11];
    const float* sg_ln2b = (const float*)d_in[12];
    const float* sg_bw   = (const float*)d_in[13];
    float* out = (float*)d_out;

    float *p_lat1, *p_lat2;
    cudaGetSymbolAddress((void**)&p_lat1, g_lat1);
    cudaGetSymbolAddress((void**)&p_lat2, g_lat2);
    __half *pbiash, *pqkvh, *pxbf, *pattbf, *pwqkv, *pwproj, *pcls, *pw1, *pl1, *pw2, *pl2, *pwb;
    cudaGetSymbolAddress((void**)&pbiash,g_biash);
    cudaGetSymbolAddress((void**)&pqkvh, g_qkvh);
    cudaGetSymbolAddress((void**)&pxbf,  g_xbf);
    cudaGetSymbolAddress((void**)&pattbf,g_attbf);
    cudaGetSymbolAddress((void**)&pwqkv, g_wqkv);
    cudaGetSymbolAddress((void**)&pwproj,g_wproj);
    cudaGetSymbolAddress((void**)&pcls,  g_clsbf);
    cudaGetSymbolAddress((void**)&pw1,   g_w1bf);
    cudaGetSymbolAddress((void**)&pl1,   g_l1bf);
    cudaGetSymbolAddress((void**)&pw2,   g_w2bf);
    cudaGetSymbolAddress((void**)&pl2,   g_l2bf);
    cudaGetSymbolAddress((void**)&pwb,   g_wbbf);

    const int SM1 = NSTG * 2 * (int)APART;   // 61440 (1-pass)
    cudaFuncSetAttribute(gemm_mma<1,1>, cudaFuncAttributeMaxDynamicSharedMemorySize, SM1);
    cudaFuncSetAttribute(gemm_mma<2,1>, cudaFuncAttributeMaxDynamicSharedMemorySize, SM1);
    cudaFuncSetAttribute(attn_kernel, cudaFuncAttributeMaxDynamicSharedMemorySize, ATT_SMEM);

    static cudaStream_t sB = nullptr;
    static cudaEvent_t evFork = nullptr, evJoin = nullptr;
    if (sB == nullptr) {
        cudaStreamCreateWithFlags(&sB, cudaStreamNonBlocking);
        cudaEventCreateWithFlags(&evFork, cudaEventDisableTiming);
        cudaEventCreateWithFlags(&evJoin, cudaEventDisableTiming);
    }

    cudaEventRecord(evFork, 0);
    cudaStreamWaitEvent(sB, evFork, 0);

    // --- side stream: bias path (single-pass fp16) + proj weight conversion ---
    conv16<<<1024, 192, 0, sB>>>(x, NT * CH, pcls, CH, 1024);
    conv16<<<512, 192, 0, sB>>>(sg_w1, CH, pw1, CH, 512);
    conv16<<<768, 192, 0, sB>>>(proj_w, CH, pwproj, CH, 768);
    gemm_mma<1,1><<<dim3(4, 8), 128, SM1, sB>>>(pcls, 768, pw1, 768, p_lat1, 512, 1024, 512, 768);
    ln_silu512<<<1024, 256, 0, sB>>>(p_lat1, sg_ln1g, sg_ln1b);
    conv16<<<1024, 128, 0, sB>>>(p_lat1, 512, pl1, 512, 1024);
    conv16<<<3072, 128, 0, sB>>>(sg_w2, 512, pw2, 512, 3072);
    gemm_mma<1,1><<<dim3(24, 8), 128, SM1, sB>>>(pl1, 512, pw2, 512, p_lat2, 3072, 1024, 3072, 512);
    ln3072<<<1024, 256, 0, sB>>>(p_lat2, sg_ln2g, sg_ln2b);
    conv16<<<12288, 64, 0, sB>>>(p_lat2, 256, pl2, 256, 12288);
    conv16<<<4352, 64, 0, sB>>>(sg_bw, 256, pwb, 256, 4225);
    gemm_mma<2,1><<<dim3(34, 96), 128, SM1, sB>>>(pl2, 256, pwb, 256, pbiash, BLDC, 12288, 4225, 256);
    cudaEventRecord(evJoin, sB);

    // --- main stream: qkv path (single-pass fp16, packed fp16 output) ---
    conv16<<<66560, 192>>>(x, CH, pxbf, CH, 66560);
    conv16<<<2304, 192>>>(qkv_w, CH, pwqkv, CH, 2304);
    gemm_mma<2,1><<<dim3(18, 520), 128, SM1>>>(pxbf, 768, pwqkv, 768, pqkvh, 2304, 66560, 2304, 768);

    cudaStreamWaitEvent(0, evJoin, 0);
    attn_kernel<<<NBATCH * NH, 160, ATT_SMEM>>>(qn_g, qn_b, kn_g, kn_b);

    // --- output projection ---
    gemm_mma<1,1><<<dim3(6, 520), 128, SM1>>>(pattbf, 768, pwproj, 768, out, 768, 66560, 768, 768);
}